// round 16
// baseline (speedup 1.0000x reference)
#include <cuda_runtime.h>
#include <cuda_bf16.h>
#include <cuda_fp16.h>
#include <math.h>
#include <stdint.h>

#define Bdim 8
#define Sdim 4096
#define Edim 1024
#define Hdim 128
#define MIN_K 32

#define NTOK (Bdim * Sdim)      // 32768
#define NEMB (NTOK * Edim)      // 33554432

#define RSCALE 2048.0f
#define INV_RSCALE (1.0f / 2048.0f)

#define NTILES 256              // 128-token scorer tiles
#define NCHUNKS 512             // 64-token filter chunks (64 per batch)

// ---------------- scratch (no device allocations allowed) ----------------
__device__ float g_logits[NTOK];
__device__ float g_z[NTOK];
__device__ float g_mask[NTOK];
// w1 split into 2 fp16 parts (part1 pre-scaled by 2048), [part][kblk(32)][n(128)][kk(32)]
__device__ unsigned char g_w1h[2 * 32 * 128 * 32 * 2];   // 524288 B
// work-stealing state (reset every launch by reset_kernel)
__device__ unsigned int g_tile_ctr;
__device__ unsigned int g_chunk_ctr;
__device__ unsigned int g_done_ctr[Bdim];
__device__ volatile unsigned int g_flag[Bdim];

// ---------------- PTX helpers (all baseline sm_80+, no 'a' features) ------
__device__ __forceinline__ uint32_t smem_u32(const void* p) {
    uint32_t a;
    asm("{ .reg .u64 t; cvta.to.shared.u64 t, %1; cvt.u32.u64 %0, t; }" : "=r"(a) : "l"(p));
    return a;
}
#define LDSM4(r0, r1, r2, r3, addr) \
    asm volatile("ldmatrix.sync.aligned.m8n8.x4.shared.b16 {%0,%1,%2,%3}, [%4];" \
        : "=r"(r0), "=r"(r1), "=r"(r2), "=r"(r3) : "r"(addr))
#define MMA_F16(c0, c1, c2, c3, a0, a1, a2, a3, b0, b1) \
    asm volatile("mma.sync.aligned.m16n8k16.row.col.f32.f16.f16.f32 " \
        "{%0,%1,%2,%3}, {%4,%5,%6,%7}, {%8,%9}, {%0,%1,%2,%3};" \
        : "+f"(c0), "+f"(c1), "+f"(c2), "+f"(c3) \
        : "r"(a0), "r"(a1), "r"(a2), "r"(a3), "r"(b0), "r"(b1))
#define CP_ASYNC16(dst, src) \
    asm volatile("cp.async.cg.shared.global [%0], [%1], 16;" :: "r"(dst), "l"(src) : "memory")
#define CP_WAIT_ALL() asm volatile("cp.async.wait_all;" ::: "memory")

// ---------------- Kernel R: reset work-stealing state ----------------
__global__ void reset_kernel()
{
    if (threadIdx.x == 0) { g_tile_ctr = 0; g_chunk_ctr = 0; }
    if (threadIdx.x < Bdim) { g_done_ctr[threadIdx.x] = 0; g_flag[threadIdx.x] = 0; }
}

// ---------------- Kernel 0: split w1 into 2 fp16 parts, [n][k] tiles ------
__global__ __launch_bounds__(256)
void prep_w1_kernel(const float* __restrict__ w1)
{
    int idx = blockIdx.x * blockDim.x + threadIdx.x;   // 0 .. 131071
    if (idx >= 32 * 128 * 32) return;
    int kblk = idx >> 12;          // 0..31
    int n    = (idx >> 5) & 127;
    int kk   = idx & 31;
    float v = w1[(size_t)(kblk * 32 + kk) * Hdim + n];

    __half h0 = __float2half_rn(v);
    float r = (v - __half2float(h0)) * RSCALE;
    __half h1 = __float2half_rn(r);

    __half* base = (__half*)g_w1h;
    base[0 * 131072 + idx] = h0;
    base[1 * 131072 + idx] = h1;
}

// ---------------- fused persistent kernel: scorer + select + filter -------
// Phase 1: work-steal 256 scorer tiles (HMMA fp16-split, 16 warps, BK=32).
//          Last finisher of each batch runs select inline, raises flag.
// Phase 2: work-steal 512 filter chunks, gated on per-batch flags.
#define ASM_OFF(st, p) ((st) * 40960u + (p) * 10240u)
#define BSM_OFF(st, p) ((st) * 40960u + 20480u + (p) * 10240u)
#define SMEM_FUSED 81920

__global__ __launch_bounds__(512, 1)
void fused_kernel(const float* __restrict__ x,
                  const float* __restrict__ b1,
                  const float* __restrict__ w2,
                  const float* __restrict__ b2,
                  const float* __restrict__ u,
                  float* __restrict__ out,
                  float* __restrict__ out_mask,
                  float* __restrict__ out_ek)
{
    extern __shared__ char smem[];
    const uint32_t sbase = smem_u32(smem);
    const int tid  = threadIdx.x;
    const int lane = tid & 31;
    const int wid  = tid >> 5;
    const int warp_m = (wid & 3) * 32;
    const int warp_n = (wid >> 2) * 32;

    __shared__ unsigned int s_work;
    __shared__ int s_last;
    __shared__ float s_red[32];

    // ldmatrix per-lane offsets (bytes), constant over tiles
    uint32_t a_off[2], b_off[2];
#pragma unroll
    for (int mf = 0; mf < 2; mf++)
        a_off[mf] = (uint32_t)(warp_m + mf * 16 + (lane & 15)) * 80u + (uint32_t)(lane >> 4) * 16u;
#pragma unroll
    for (int q = 0; q < 2; q++)
        b_off[q] = (uint32_t)(warp_n + q * 16 + (lane & 7) + ((lane >> 4) & 1) * 8) * 80u
                 + (uint32_t)((lane >> 3) & 1) * 16u;

    const int xrow = tid >> 2;
    const int xq   = tid & 3;
    const uint32_t a_sts = (uint32_t)xrow * 80u + (uint32_t)xq * 16u;
    const uint32_t b_sts = (uint32_t)(tid >> 2) * 80u + (uint32_t)(tid & 3) * 16u;
    const size_t b_src_off = (size_t)tid * 16;

    // ================= Phase 1: scorer tiles =================
    while (true) {
        if (tid == 0) s_work = atomicAdd(&g_tile_ctr, 1u);
        __syncthreads();
        const unsigned tile = s_work;
        if (tile >= NTILES) break;
        const int block_m = (int)tile * 128;
        const int batch = (int)(tile >> 5);
        const float* xg = x + (size_t)(block_m + xrow) * Edim + xq * 8;

        float accA[2][4][4], accB[2][4][4];
#pragma unroll
        for (int mf = 0; mf < 2; mf++)
#pragma unroll
            for (int nf = 0; nf < 4; nf++)
#pragma unroll
                for (int e = 0; e < 4; e++) { accA[mf][nf][e] = 0.f; accB[mf][nf][e] = 0.f; }

        float xf[8];

        // ---- prologue: stage 0 ----
        {
#pragma unroll
            for (int q = 0; q < 2; q++) {
                float4 f = *(const float4*)(xg + q * 4);
                xf[q * 4 + 0] = f.x; xf[q * 4 + 1] = f.y; xf[q * 4 + 2] = f.z; xf[q * 4 + 3] = f.w;
            }
#pragma unroll
            for (int p = 0; p < 2; p++) {
                const char* src = (const char*)g_w1h + (size_t)p * 262144 + b_src_off;
                CP_ASYNC16(sbase + BSM_OFF(0, p) + b_sts, src);
            }
            unsigned short s0[8], s1[8];
#pragma unroll
            for (int e = 0; e < 8; e++) {
                __half h0 = __float2half_rn(xf[e]);
                float r = (xf[e] - __half2float(h0)) * RSCALE;
                __half h1 = __float2half_rn(r);
                s0[e] = __half_as_ushort(h0);
                s1[e] = __half_as_ushort(h1);
            }
            *(uint4*)(smem + ASM_OFF(0, 0) + a_sts) =
                make_uint4((uint32_t)s0[0] | ((uint32_t)s0[1] << 16),
                           (uint32_t)s0[2] | ((uint32_t)s0[3] << 16),
                           (uint32_t)s0[4] | ((uint32_t)s0[5] << 16),
                           (uint32_t)s0[6] | ((uint32_t)s0[7] << 16));
            *(uint4*)(smem + ASM_OFF(0, 1) + a_sts) =
                make_uint4((uint32_t)s1[0] | ((uint32_t)s1[1] << 16),
                           (uint32_t)s1[2] | ((uint32_t)s1[3] << 16),
                           (uint32_t)s1[4] | ((uint32_t)s1[5] << 16),
                           (uint32_t)s1[6] | ((uint32_t)s1[7] << 16));
            CP_WAIT_ALL();
            __syncthreads();
        }

        // ---- main loop: 32 iters of BK=32 ----
        for (int it = 0; it < 32; it++) {
            const int st = it & 1;
            const int nst = st ^ 1;

            if (it < 31) {
#pragma unroll
                for (int q = 0; q < 2; q++) {
                    float4 f = *(const float4*)(xg + (it + 1) * 32 + q * 4);
                    xf[q * 4 + 0] = f.x; xf[q * 4 + 1] = f.y; xf[q * 4 + 2] = f.z; xf[q * 4 + 3] = f.w;
                }
#pragma unroll
                for (int p = 0; p < 2; p++) {
                    const char* src = (const char*)g_w1h + (size_t)p * 262144
                                    + (size_t)(it + 1) * 8192 + b_src_off;
                    CP_ASYNC16(sbase + BSM_OFF(nst, p) + b_sts, src);
                }
            }

#pragma unroll
            for (int k16 = 0; k16 < 2; k16++) {
                const uint32_t kb = (uint32_t)k16 * 32u;
                uint32_t a0r[8], a1r[8], br[8];

#pragma unroll
                for (int q = 0; q < 2; q++)
                    LDSM4(br[q * 4 + 0], br[q * 4 + 1], br[q * 4 + 2], br[q * 4 + 3],
                          sbase + BSM_OFF(st, 0) + b_off[q] + kb);
                LDSM4(a0r[0], a0r[1], a0r[2], a0r[3], sbase + ASM_OFF(st, 0) + a_off[0] + kb);
                LDSM4(a0r[4], a0r[5], a0r[6], a0r[7], sbase + ASM_OFF(st, 0) + a_off[1] + kb);

#pragma unroll
                for (int mf = 0; mf < 2; mf++)
#pragma unroll
                    for (int nf = 0; nf < 4; nf++) {
                        const int q = nf >> 1, pr = nf & 1;
                        MMA_F16(accA[mf][nf][0], accA[mf][nf][1], accA[mf][nf][2], accA[mf][nf][3],
                                a0r[mf * 4 + 0], a0r[mf * 4 + 1], a0r[mf * 4 + 2], a0r[mf * 4 + 3],
                                br[q * 4 + pr * 2], br[q * 4 + pr * 2 + 1]);
                    }

                LDSM4(a1r[0], a1r[1], a1r[2], a1r[3], sbase + ASM_OFF(st, 1) + a_off[0] + kb);
                LDSM4(a1r[4], a1r[5], a1r[6], a1r[7], sbase + ASM_OFF(st, 1) + a_off[1] + kb);
#pragma unroll
                for (int mf = 0; mf < 2; mf++)
#pragma unroll
                    for (int nf = 0; nf < 4; nf++) {
                        const int q = nf >> 1, pr = nf & 1;
                        MMA_F16(accB[mf][nf][0], accB[mf][nf][1], accB[mf][nf][2], accB[mf][nf][3],
                                a1r[mf * 4 + 0], a1r[mf * 4 + 1], a1r[mf * 4 + 2], a1r[mf * 4 + 3],
                                br[q * 4 + pr * 2], br[q * 4 + pr * 2 + 1]);
                    }

#pragma unroll
                for (int q = 0; q < 2; q++)
                    LDSM4(br[q * 4 + 0], br[q * 4 + 1], br[q * 4 + 2], br[q * 4 + 3],
                          sbase + BSM_OFF(st, 1) + b_off[q] + kb);
#pragma unroll
                for (int mf = 0; mf < 2; mf++)
#pragma unroll
                    for (int nf = 0; nf < 4; nf++) {
                        const int q = nf >> 1, pr = nf & 1;
                        MMA_F16(accB[mf][nf][0], accB[mf][nf][1], accB[mf][nf][2], accB[mf][nf][3],
                                a0r[mf * 4 + 0], a0r[mf * 4 + 1], a0r[mf * 4 + 2], a0r[mf * 4 + 3],
                                br[q * 4 + pr * 2], br[q * 4 + pr * 2 + 1]);
                    }
            }

            if (it < 31) {
                unsigned short s0[8], s1[8];
#pragma unroll
                for (int e = 0; e < 8; e++) {
                    __half h0 = __float2half_rn(xf[e]);
                    float r = (xf[e] - __half2float(h0)) * RSCALE;
                    __half h1 = __float2half_rn(r);
                    s0[e] = __half_as_ushort(h0);
                    s1[e] = __half_as_ushort(h1);
                }
                *(uint4*)(smem + ASM_OFF(nst, 0) + a_sts) =
                    make_uint4((uint32_t)s0[0] | ((uint32_t)s0[1] << 16),
                               (uint32_t)s0[2] | ((uint32_t)s0[3] << 16),
                               (uint32_t)s0[4] | ((uint32_t)s0[5] << 16),
                               (uint32_t)s0[6] | ((uint32_t)s0[7] << 16));
                *(uint4*)(smem + ASM_OFF(nst, 1) + a_sts) =
                    make_uint4((uint32_t)s1[0] | ((uint32_t)s1[1] << 16),
                               (uint32_t)s1[2] | ((uint32_t)s1[3] << 16),
                               (uint32_t)s1[4] | ((uint32_t)s1[5] << 16),
                               (uint32_t)s1[6] | ((uint32_t)s1[7] << 16));
            }
            CP_WAIT_ALL();
            __syncthreads();
        }

        // ---- tile epilogue: combine splits, relu + dot(w2) ----
        {
            float b1v[8], w2v[8];
#pragma unroll
            for (int nf = 0; nf < 4; nf++)
#pragma unroll
                for (int j = 0; j < 2; j++) {
                    const int n = warp_n + nf * 8 + 2 * (lane & 3) + j;
                    b1v[nf * 2 + j] = b1[n];
                    w2v[nf * 2 + j] = w2[n];
                }
            float* red = (float*)smem;   // [4][128] floats
#pragma unroll
            for (int mf = 0; mf < 2; mf++)
#pragma unroll
                for (int half = 0; half < 2; half++) {
                    float s = 0.f;
#pragma unroll
                    for (int nf = 0; nf < 4; nf++)
#pragma unroll
                        for (int j = 0; j < 2; j++) {
                            float v = fmaf(accB[mf][nf][half * 2 + j], INV_RSCALE,
                                           accA[mf][nf][half * 2 + j]) + b1v[nf * 2 + j];
                            v = fmaxf(v, 0.f);
                            s = fmaf(v, w2v[nf * 2 + j], s);
                        }
                    s += __shfl_xor_sync(0xffffffffu, s, 1);
                    s += __shfl_xor_sync(0xffffffffu, s, 2);
                    if ((lane & 3) == 0)
                        red[(wid >> 2) * 128 + warp_m + mf * 16 + half * 8 + (lane >> 2)] = s;
                }
            __syncthreads();
            if (tid < 128)
                g_logits[block_m + tid] = red[tid] + red[128 + tid] + red[256 + tid]
                                        + red[384 + tid] + b2[0];
            __syncthreads();
        }

        // ---- batch bookkeeping: last finisher runs select ----
        if (tid == 0) {
            __threadfence();
            unsigned d = atomicAdd(&g_done_ctr[batch], 1u);
            s_last = (d == 31u);
        }
        __syncthreads();

        if (s_last) {
            // ===== inline select for `batch` (512 threads) =====
            float* zs = (float*)smem;            // 16 KB, scorer bufs dead
            const float* urow = u + (size_t)batch * Sdim;

            float sig = 0.f;
            for (int i = tid; i < Sdim; i += 512) {
                float l = __ldcg(&g_logits[batch * Sdim + i]);
                float g = -logf(-logf(urow[i]));
                float z = l + g;
                g_z[batch * Sdim + i] = z;
                zs[i] = z;
                sig += 1.f / (1.f + expf(-l));
            }
#pragma unroll
            for (int off = 16; off; off >>= 1) sig += __shfl_xor_sync(~0u, sig, off);
            if (lane == 0) s_red[wid] = sig;
            __syncthreads();
            if (tid < 32) {
                float v = (tid < 16) ? s_red[tid] : 0.f;
#pragma unroll
                for (int off = 8; off; off >>= 1) v += __shfl_xor_sync(~0u, v, off);
                if (tid == 0) s_red[0] = v;
            }
            __syncthreads();
            const float ek = s_red[0];
            int k = (int)ek;
            if (k < MIN_K) k = MIN_K;

            for (int size = 2; size <= Sdim; size <<= 1) {
                for (int stride = size >> 1; stride > 0; stride >>= 1) {
                    __syncthreads();
                    for (int i = tid; i < Sdim; i += 512) {
                        int j = i ^ stride;
                        if (j > i) {
                            float a = zs[i], c = zs[j];
                            bool up = ((i & size) == 0);
                            if ((a > c) == up) { zs[i] = c; zs[j] = a; }
                        }
                    }
                }
            }
            __syncthreads();

            int idx = Sdim - k;
            if (idx < 0) idx = 0;
            const float thr = zs[idx];

            for (int i = tid; i < Sdim; i += 512) {
                float m = (g_z[batch * Sdim + i] >= thr) ? 1.0f : 0.0f;
                g_mask[batch * Sdim + i] = m;
                if (out_mask) out_mask[batch * Sdim + i] = m;
            }
            if (tid == 0) {
                if (out_ek) out_ek[batch] = ek;
                __threadfence();
                g_flag[batch] = 1u;     // release
            }
        }
        __syncthreads();
    }

    // ================= Phase 2: filter chunks =================
    const float4* x4 = (const float4*)x;
    float4* o4 = (float4*)out;
    while (true) {
        if (tid == 0) s_work = atomicAdd(&g_chunk_ctr, 1u);
        __syncthreads();
        const unsigned c = s_work;
        if (c >= NCHUNKS) break;
        const int batch = (int)(c >> 6);
        if (tid == 0) {
            while (g_flag[batch] == 0u) __nanosleep(200);
        }
        __syncthreads();
        __threadfence();   // acquire: order mask reads after flag

        const size_t base = (size_t)c * 16384;   // 64 tokens * 256 float4
#pragma unroll 4
        for (int j = 0; j < 32; j++) {
            size_t i = base + tid + (size_t)j * 512;
            float m = __ldcg(&g_mask[i >> 8]);
            float4 v;
            if (m != 0.f) {
                v = x4[i];
                v.x *= m; v.y *= m; v.z *= m; v.w *= m;
            } else {
                v.x = 0.f; v.y = 0.f; v.z = 0.f; v.w = 0.f;
            }
            __stcs(&o4[i], v);
        }
    }
}

// ---------------- launch ----------------
extern "C" void kernel_launch(void* const* d_in, const int* in_sizes, int n_in,
                              void* d_out, int out_size)
{
    const float* x  = (const float*)d_in[0];
    const float* w1 = (const float*)d_in[1];
    const float* b1 = (const float*)d_in[2];
    const float* w2 = (const float*)d_in[3];
    const float* b2 = (const float*)d_in[4];
    const float* u  = (const float*)d_in[5];
    float* out = (float*)d_out;

    float* out_mask = (out_size >= NEMB + NTOK) ? (out + NEMB) : nullptr;
    float* out_ek   = (out_size >= NEMB + NTOK + Bdim) ? (out + NEMB + NTOK) : nullptr;

    int dev = 0, sms = 148;
    cudaGetDevice(&dev);
    cudaDeviceGetAttribute(&sms, cudaDevAttrMultiProcessorCount, dev);
    if (sms < 1) sms = 148;
    if (sms > NTILES) sms = NTILES;

    cudaFuncSetAttribute(fused_kernel,
                         cudaFuncAttributeMaxDynamicSharedMemorySize, SMEM_FUSED);

    reset_kernel<<<1, 32>>>();
    prep_w1_kernel<<<512, 256>>>(w1);
    fused_kernel<<<sms, 512, SMEM_FUSED>>>(x, b1, w2, b2, u, out, out_mask, out_ek);
}

// round 17
// speedup vs baseline: 1.1738x; 1.1738x over previous
#include <cuda_runtime.h>
#include <cuda_bf16.h>
#include <cuda_fp16.h>
#include <math.h>
#include <stdint.h>

#define Bdim 8
#define Sdim 4096
#define Edim 1024
#define Hdim 128
#define MIN_K 32

#define NTOK (Bdim * Sdim)      // 32768
#define NEMB (NTOK * Edim)      // 33554432

#define RSCALE 2048.0f
#define INV_RSCALE (1.0f / 2048.0f)

// ---------------- scratch (no device allocations allowed) ----------------
__device__ float g_z[NTOK];
__device__ float g_mask[NTOK];
__device__ float g_sigpart[256];     // per-tile sigmoid partial sums
// w1 split into 2 fp16 parts (part1 pre-scaled by 2048), [part][kblk(32)][n(128)][kk(32)]
__device__ unsigned char g_w1h[2 * 32 * 128 * 32 * 2];   // 524288 B

// ---------------- PTX helpers (all baseline sm_80+, no 'a' features) ------
__device__ __forceinline__ uint32_t smem_u32(const void* p) {
    uint32_t a;
    asm("{ .reg .u64 t; cvta.to.shared.u64 t, %1; cvt.u32.u64 %0, t; }" : "=r"(a) : "l"(p));
    return a;
}
#define LDSM4(r0, r1, r2, r3, addr) \
    asm volatile("ldmatrix.sync.aligned.m8n8.x4.shared.b16 {%0,%1,%2,%3}, [%4];" \
        : "=r"(r0), "=r"(r1), "=r"(r2), "=r"(r3) : "r"(addr))
#define MMA_F16(c0, c1, c2, c3, a0, a1, a2, a3, b0, b1) \
    asm volatile("mma.sync.aligned.m16n8k16.row.col.f32.f16.f16.f32 " \
        "{%0,%1,%2,%3}, {%4,%5,%6,%7}, {%8,%9}, {%0,%1,%2,%3};" \
        : "+f"(c0), "+f"(c1), "+f"(c2), "+f"(c3) \
        : "r"(a0), "r"(a1), "r"(a2), "r"(a3), "r"(b0), "r"(b1))
#define CP_ASYNC16(dst, src) \
    asm volatile("cp.async.cg.shared.global [%0], [%1], 16;" :: "r"(dst), "l"(src) : "memory")
#define CP_WAIT_ALL() asm volatile("cp.async.wait_all;" ::: "memory")

// ---------------- Kernel 0: split w1 into 2 fp16 parts, [n][k] tiles ------
__global__ __launch_bounds__(256)
void prep_w1_kernel(const float* __restrict__ w1)
{
    int idx = blockIdx.x * blockDim.x + threadIdx.x;   // 0 .. 131071
    if (idx >= 32 * 128 * 32) return;
    int kblk = idx >> 12;          // 0..31
    int n    = (idx >> 5) & 127;
    int kk   = idx & 31;
    float v = w1[(size_t)(kblk * 32 + kk) * Hdim + n];

    __half h0 = __float2half_rn(v);
    float r = (v - __half2float(h0)) * RSCALE;
    __half h1 = __float2half_rn(r);

    __half* base = (__half*)g_w1h;
    base[0 * 131072 + idx] = h0;
    base[1 * 131072 + idx] = h1;
}

// ---------------- Kernel 1: HMMA fp16 split scorer (16 warps) ----------------
// C[128 tok][128 H] per CTA, 512 threads, warp grid 4(M)x4(N), warp tile 32x32.
// a = a0 + a1'/2048, b = b0 + b1'/2048. 3 passes:
//   a0*b0 -> accA ; a1'*b0 -> accB ; a0*b1' -> accB.  logits = accA + accB/2048.
// Epilogue additionally emits z = logit + gumbel(u) and the tile's sigmoid
// partial sum (select no longer touches logits).
// smem tiles: [128 rows][32+8 fp16] = 80 B rows (ldmatrix conflict-free).
#define ASM_OFF(st, p) ((st) * 40960u + (p) * 10240u)
#define BSM_OFF(st, p) ((st) * 40960u + 20480u + (p) * 10240u)
#define SMEM_HMMA 81920

__global__ __launch_bounds__(512, 1)
void scorer_hmma_kernel(const float* __restrict__ x,
                        const float* __restrict__ b1,
                        const float* __restrict__ w2,
                        const float* __restrict__ b2,
                        const float* __restrict__ u)
{
    extern __shared__ char smem[];
    const uint32_t sbase = smem_u32(smem);
    const int tid  = threadIdx.x;
    const int lane = tid & 31;
    const int wid  = tid >> 5;
    const int warp_m = (wid & 3) * 32;
    const int warp_n = (wid >> 2) * 32;
    const int block_m = blockIdx.x * 128;

    // ldmatrix per-lane offsets (bytes), constant over iters
    uint32_t a_off[2], b_off[2];
#pragma unroll
    for (int mf = 0; mf < 2; mf++)
        a_off[mf] = (uint32_t)(warp_m + mf * 16 + (lane & 15)) * 80u + (uint32_t)(lane >> 4) * 16u;
#pragma unroll
    for (int q = 0; q < 2; q++)
        b_off[q] = (uint32_t)(warp_n + q * 16 + (lane & 7) + ((lane >> 4) & 1) * 8) * 80u
                 + (uint32_t)((lane >> 3) & 1) * 16u;

    // x load mapping: row = tid>>2 (0..127), k-quarter = tid&3 (8 floats)
    const int xrow = tid >> 2;
    const int xq   = tid & 3;
    const float* xg = x + (size_t)(block_m + xrow) * Edim + xq * 8;
    const uint32_t a_sts = (uint32_t)xrow * 80u + (uint32_t)xq * 16u;

    // B cp.async mapping: 16 B per thread per part-tile
    const uint32_t b_sts = (uint32_t)(tid >> 2) * 80u + (uint32_t)(tid & 3) * 16u;
    const size_t b_src_off = (size_t)tid * 16;

    float accA[2][4][4], accB[2][4][4];
#pragma unroll
    for (int mf = 0; mf < 2; mf++)
#pragma unroll
        for (int nf = 0; nf < 4; nf++)
#pragma unroll
            for (int e = 0; e < 4; e++) { accA[mf][nf][e] = 0.f; accB[mf][nf][e] = 0.f; }

    float xf[8];

    // ---- prologue: stage 0 ----
    {
#pragma unroll
        for (int q = 0; q < 2; q++) {
            float4 f = *(const float4*)(xg + q * 4);
            xf[q * 4 + 0] = f.x; xf[q * 4 + 1] = f.y; xf[q * 4 + 2] = f.z; xf[q * 4 + 3] = f.w;
        }
#pragma unroll
        for (int p = 0; p < 2; p++) {
            const char* src = (const char*)g_w1h + (size_t)p * 262144 + b_src_off;
            CP_ASYNC16(sbase + BSM_OFF(0, p) + b_sts, src);
        }
        unsigned short s0[8], s1[8];
#pragma unroll
        for (int e = 0; e < 8; e++) {
            __half h0 = __float2half_rn(xf[e]);
            float r = (xf[e] - __half2float(h0)) * RSCALE;
            __half h1 = __float2half_rn(r);
            s0[e] = __half_as_ushort(h0);
            s1[e] = __half_as_ushort(h1);
        }
        *(uint4*)(smem + ASM_OFF(0, 0) + a_sts) =
            make_uint4((uint32_t)s0[0] | ((uint32_t)s0[1] << 16),
                       (uint32_t)s0[2] | ((uint32_t)s0[3] << 16),
                       (uint32_t)s0[4] | ((uint32_t)s0[5] << 16),
                       (uint32_t)s0[6] | ((uint32_t)s0[7] << 16));
        *(uint4*)(smem + ASM_OFF(0, 1) + a_sts) =
            make_uint4((uint32_t)s1[0] | ((uint32_t)s1[1] << 16),
                       (uint32_t)s1[2] | ((uint32_t)s1[3] << 16),
                       (uint32_t)s1[4] | ((uint32_t)s1[5] << 16),
                       (uint32_t)s1[6] | ((uint32_t)s1[7] << 16));
        CP_WAIT_ALL();
        __syncthreads();
    }

    // ---- main loop ----
    for (int it = 0; it < 32; it++) {
        const int st = it & 1;
        const int nst = st ^ 1;

        if (it < 31) {
            // prefetch next x (LDG latency hidden by HMMA below)
#pragma unroll
            for (int q = 0; q < 2; q++) {
                float4 f = *(const float4*)(xg + (it + 1) * 32 + q * 4);
                xf[q * 4 + 0] = f.x; xf[q * 4 + 1] = f.y; xf[q * 4 + 2] = f.z; xf[q * 4 + 3] = f.w;
            }
            // async B for next stage
#pragma unroll
            for (int p = 0; p < 2; p++) {
                const char* src = (const char*)g_w1h + (size_t)p * 262144
                                + (size_t)(it + 1) * 8192 + b_src_off;
                CP_ASYNC16(sbase + BSM_OFF(nst, p) + b_sts, src);
            }
        }

        // ---- HMMA: 2 k16-steps x 3 passes, a0/b0 frag reuse ----
#pragma unroll
        for (int k16 = 0; k16 < 2; k16++) {
            const uint32_t kb = (uint32_t)k16 * 32u;
            uint32_t a0r[8], a1r[8], br[8];

            // b0 fragments (32 n-cols: 2 x LDSM4)
#pragma unroll
            for (int q = 0; q < 2; q++)
                LDSM4(br[q * 4 + 0], br[q * 4 + 1], br[q * 4 + 2], br[q * 4 + 3],
                      sbase + BSM_OFF(st, 0) + b_off[q] + kb);
            // a0 fragments (kept for pass 3)
            LDSM4(a0r[0], a0r[1], a0r[2], a0r[3], sbase + ASM_OFF(st, 0) + a_off[0] + kb);
            LDSM4(a0r[4], a0r[5], a0r[6], a0r[7], sbase + ASM_OFF(st, 0) + a_off[1] + kb);

            // pass 1: a0*b0 -> accA
#pragma unroll
            for (int mf = 0; mf < 2; mf++)
#pragma unroll
                for (int nf = 0; nf < 4; nf++) {
                    const int q = nf >> 1, pr = nf & 1;
                    MMA_F16(accA[mf][nf][0], accA[mf][nf][1], accA[mf][nf][2], accA[mf][nf][3],
                            a0r[mf * 4 + 0], a0r[mf * 4 + 1], a0r[mf * 4 + 2], a0r[mf * 4 + 3],
                            br[q * 4 + pr * 2], br[q * 4 + pr * 2 + 1]);
                }

            // pass 2: a1'*b0 -> accB
            LDSM4(a1r[0], a1r[1], a1r[2], a1r[3], sbase + ASM_OFF(st, 1) + a_off[0] + kb);
            LDSM4(a1r[4], a1r[5], a1r[6], a1r[7], sbase + ASM_OFF(st, 1) + a_off[1] + kb);
#pragma unroll
            for (int mf = 0; mf < 2; mf++)
#pragma unroll
                for (int nf = 0; nf < 4; nf++) {
                    const int q = nf >> 1, pr = nf & 1;
                    MMA_F16(accB[mf][nf][0], accB[mf][nf][1], accB[mf][nf][2], accB[mf][nf][3],
                            a1r[mf * 4 + 0], a1r[mf * 4 + 1], a1r[mf * 4 + 2], a1r[mf * 4 + 3],
                            br[q * 4 + pr * 2], br[q * 4 + pr * 2 + 1]);
                }

            // pass 3: a0*b1' -> accB (b1' fragments overwrite br)
#pragma unroll
            for (int q = 0; q < 2; q++)
                LDSM4(br[q * 4 + 0], br[q * 4 + 1], br[q * 4 + 2], br[q * 4 + 3],
                      sbase + BSM_OFF(st, 1) + b_off[q] + kb);
#pragma unroll
            for (int mf = 0; mf < 2; mf++)
#pragma unroll
                for (int nf = 0; nf < 4; nf++) {
                    const int q = nf >> 1, pr = nf & 1;
                    MMA_F16(accB[mf][nf][0], accB[mf][nf][1], accB[mf][nf][2], accB[mf][nf][3],
                            a0r[mf * 4 + 0], a0r[mf * 4 + 1], a0r[mf * 4 + 2], a0r[mf * 4 + 3],
                            br[q * 4 + pr * 2], br[q * 4 + pr * 2 + 1]);
                }
        }

        if (it < 31) {
            // convert prefetched x, store to next stage
            unsigned short s0[8], s1[8];
#pragma unroll
            for (int e = 0; e < 8; e++) {
                __half h0 = __float2half_rn(xf[e]);
                float r = (xf[e] - __half2float(h0)) * RSCALE;
                __half h1 = __float2half_rn(r);
                s0[e] = __half_as_ushort(h0);
                s1[e] = __half_as_ushort(h1);
            }
            *(uint4*)(smem + ASM_OFF(nst, 0) + a_sts) =
                make_uint4((uint32_t)s0[0] | ((uint32_t)s0[1] << 16),
                           (uint32_t)s0[2] | ((uint32_t)s0[3] << 16),
                           (uint32_t)s0[4] | ((uint32_t)s0[5] << 16),
                           (uint32_t)s0[6] | ((uint32_t)s0[7] << 16));
            *(uint4*)(smem + ASM_OFF(nst, 1) + a_sts) =
                make_uint4((uint32_t)s1[0] | ((uint32_t)s1[1] << 16),
                           (uint32_t)s1[2] | ((uint32_t)s1[3] << 16),
                           (uint32_t)s1[4] | ((uint32_t)s1[5] << 16),
                           (uint32_t)s1[6] | ((uint32_t)s1[7] << 16));
        }
        CP_WAIT_ALL();
        __syncthreads();
    }

    // ---- epilogue: combine split accumulators, relu + dot(w2) ----
    float b1v[8], w2v[8];
#pragma unroll
    for (int nf = 0; nf < 4; nf++)
#pragma unroll
        for (int j = 0; j < 2; j++) {
            const int n = warp_n + nf * 8 + 2 * (lane & 3) + j;
            b1v[nf * 2 + j] = b1[n];
            w2v[nf * 2 + j] = w2[n];
        }

    float* red = (float*)smem;   // [4][128] floats = 2 KB, + [4] sig partials
#pragma unroll
    for (int mf = 0; mf < 2; mf++)
#pragma unroll
        for (int half = 0; half < 2; half++) {
            float s = 0.f;
#pragma unroll
            for (int nf = 0; nf < 4; nf++)
#pragma unroll
                for (int j = 0; j < 2; j++) {
                    float v = fmaf(accB[mf][nf][half * 2 + j], INV_RSCALE,
                                   accA[mf][nf][half * 2 + j]) + b1v[nf * 2 + j];
                    v = fmaxf(v, 0.f);
                    s = fmaf(v, w2v[nf * 2 + j], s);
                }
            s += __shfl_xor_sync(0xffffffffu, s, 1);
            s += __shfl_xor_sync(0xffffffffu, s, 2);
            if ((lane & 3) == 0)
                red[(wid >> 2) * 128 + warp_m + mf * 16 + half * 8 + (lane >> 2)] = s;
        }
    __syncthreads();

    // logits -> z (gumbel) + per-tile sigmoid partial, all in-register
    if (tid < 128) {
        float l = red[tid] + red[128 + tid] + red[256 + tid] + red[384 + tid] + b2[0];
        float gz = -logf(-logf(u[block_m + tid]));
        g_z[block_m + tid] = l + gz;
        float sig = 1.f / (1.f + expf(-l));
#pragma unroll
        for (int off = 16; off; off >>= 1) sig += __shfl_xor_sync(0xffffffffu, sig, off);
        if (lane == 0) red[512 + (tid >> 5)] = sig;
    }
    __syncthreads();
    if (tid == 0)
        g_sigpart[blockIdx.x] = (red[512] + red[513]) + (red[514] + red[515]);
}

// ---------------- Kernel 2: expected_k + top-k threshold + mask ----------------
// One block (1024 threads) per batch row. z already computed by scorer.
__global__ __launch_bounds__(1024)
void select_kernel(float* __restrict__ out_mask,
                   float* __restrict__ out_ek)
{
    __shared__ float zs[Sdim];
    __shared__ float s_ek;

    const int b = blockIdx.x;
    const int tid = threadIdx.x;

    for (int i = tid; i < Sdim; i += 1024)
        zs[i] = g_z[b * Sdim + i];

    if (tid == 0) {
        float ek = 0.f;
#pragma unroll
        for (int t = 0; t < 32; t++) ek += g_sigpart[b * 32 + t];
        s_ek = ek;
    }

    // bitonic ascending sort of zs[0..4095]
    for (int size = 2; size <= Sdim; size <<= 1) {
        for (int stride = size >> 1; stride > 0; stride >>= 1) {
            __syncthreads();
            for (int i = tid; i < Sdim; i += 1024) {
                int j = i ^ stride;
                if (j > i) {
                    float a = zs[i], c = zs[j];
                    bool up = ((i & size) == 0);
                    if ((a > c) == up) { zs[i] = c; zs[j] = a; }
                }
            }
        }
    }
    __syncthreads();

    const float ek = s_ek;
    int k = (int)ek;                 // astype(int32): truncation toward zero
    if (k < MIN_K) k = MIN_K;
    int idx = Sdim - k;
    if (idx < 0) idx = 0;
    const float thr = zs[idx];       // k-th largest

    for (int i = tid; i < Sdim; i += 1024) {
        float m = (g_z[b * Sdim + i] >= thr) ? 1.0f : 0.0f;
        g_mask[b * Sdim + i] = m;
        if (out_mask) out_mask[b * Sdim + i] = m;
    }
    if (tid == 0 && out_ek) out_ek[b] = ek;
}

// ---------------- Kernel 3: filtered = x * mask (MLP-4 grid-stride) --------
// n4 = 8,388,608 = 4 * (4096 blocks * 512 threads): each thread owns exactly
// 4 independent elements; all mask loads issue before the (warp-uniform)
// predicated x loads, then 4 streaming stores.
__global__ __launch_bounds__(512)
void filter_kernel(const float4* __restrict__ x, float4* __restrict__ out)
{
    const int t = blockIdx.x * 512 + threadIdx.x;
    const int STRIDE = 4096 * 512;

    int idx[4];
    float m[4];
#pragma unroll
    for (int j = 0; j < 4; j++) {
        idx[j] = t + j * STRIDE;
        m[j] = g_mask[idx[j] >> 8];         // 4 independent L2 hits
    }
    float4 v[4];
#pragma unroll
    for (int j = 0; j < 4; j++) {
        if (m[j] != 0.f) {
            v[j] = x[idx[j]];
            v[j].x *= m[j]; v[j].y *= m[j]; v[j].z *= m[j]; v[j].w *= m[j];
        } else {
            v[j].x = 0.f; v[j].y = 0.f; v[j].z = 0.f; v[j].w = 0.f;
        }
    }
#pragma unroll
    for (int j = 0; j < 4; j++)
        __stcs(&out[idx[j]], v[j]);          // streaming: out never re-read
}

// ---------------- launch ----------------
extern "C" void kernel_launch(void* const* d_in, const int* in_sizes, int n_in,
                              void* d_out, int out_size)
{
    const float* x  = (const float*)d_in[0];
    const float* w1 = (const float*)d_in[1];
    const float* b1 = (const float*)d_in[2];
    const float* w2 = (const float*)d_in[3];
    const float* b2 = (const float*)d_in[4];
    const float* u  = (const float*)d_in[5];
    float* out = (float*)d_out;

    float* out_mask = (out_size >= NEMB + NTOK) ? (out + NEMB) : nullptr;
    float* out_ek   = (out_size >= NEMB + NTOK + Bdim) ? (out + NEMB + NTOK) : nullptr;

    cudaFuncSetAttribute(scorer_hmma_kernel,
                         cudaFuncAttributeMaxDynamicSharedMemorySize, SMEM_HMMA);

    prep_w1_kernel<<<512, 256>>>(w1);
    scorer_hmma_kernel<<<NTOK / 128, 512, SMEM_HMMA>>>(x, b1, w2, b2, u);
    select_kernel<<<Bdim, 1024>>>(out_mask, out_ek);
    filter_kernel<<<4096, 512>>>((const float4*)x, (float4*)out);
}